// round 8
// baseline (speedup 1.0000x reference)
#include <cuda_runtime.h>
#include <cstdint>
#include <cstddef>

// B=4,H=16,S=2048,D=64 fp32.  out = [ctx (64*2048*64)] ++ [attn (64*2048*2048)]
// score = QK^T/8 ; attn = relu(score) ; ctx = attn @ V
// bf16x3 emulated-fp32 mma.sync; cp.async fp32 staging (R6 structure);
// 512 threads / 16 warps (4x4 warp grid) for 2x occupancy.
#define S_LEN 2048
#define HDIM  64
#define BLK   128
#define NT    512
#define NTILES (S_LEN / BLK)
#define NBH   64
#define CTX_ELEMS 8388608LL

#define OFF_QH 0
#define OFF_QL 16384
#define OFF_KH 32768
#define OFF_KL 49152
#define OFF_VH 65536
#define OFF_VL 81920
#define STAGE_K 98304
#define STAGE_V 131072
#define SMEM_BYTES 163840
#define RED_STRIDE 72
#define RED_LSZ (128 * RED_STRIDE)   // floats per reduction layer

__device__ __forceinline__ uint32_t cvta_smem(const void* p) {
    uint32_t a;
    asm("{ .reg .u64 t; cvta.to.shared.u64 t, %1; cvt.u32.u64 %0, t; }" : "=r"(a) : "l"(p));
    return a;
}
__device__ __forceinline__ void ldsm4(uint32_t r[4], uint32_t a) {
    asm volatile("ldmatrix.sync.aligned.m8n8.x4.shared.b16 {%0,%1,%2,%3}, [%4];"
                 : "=r"(r[0]), "=r"(r[1]), "=r"(r[2]), "=r"(r[3]) : "r"(a));
}
__device__ __forceinline__ void ldsm4t(uint32_t r[4], uint32_t a) {
    asm volatile("ldmatrix.sync.aligned.m8n8.x4.trans.shared.b16 {%0,%1,%2,%3}, [%4];"
                 : "=r"(r[0]), "=r"(r[1]), "=r"(r[2]), "=r"(r[3]) : "r"(a));
}
__device__ __forceinline__ void mma16816(float c[4], const uint32_t a[4],
                                         uint32_t b0, uint32_t b1) {
    asm volatile("mma.sync.aligned.m16n8k16.row.col.f32.bf16.bf16.f32 "
                 "{%0,%1,%2,%3}, {%4,%5,%6,%7}, {%8,%9}, {%0,%1,%2,%3};"
                 : "+f"(c[0]), "+f"(c[1]), "+f"(c[2]), "+f"(c[3])
                 : "r"(a[0]), "r"(a[1]), "r"(a[2]), "r"(a[3]), "r"(b0), "r"(b1));
}
__device__ __forceinline__ uint32_t packbf(float lo, float hi) {
    uint32_t d;
    asm("cvt.rn.bf16x2.f32 %0, %1, %2;" : "=r"(d) : "f"(hi), "f"(lo));
    return d;
}
__device__ __forceinline__ void split_store(char* smc, int offH, int offL,
                                            int row, int c4f, float4 v) {
    uint32_t h0 = packbf(v.x, v.y);
    uint32_t h1 = packbf(v.z, v.w);
    float fx = __uint_as_float(h0 << 16), fy = __uint_as_float(h0 & 0xffff0000u);
    float fz = __uint_as_float(h1 << 16), fw = __uint_as_float(h1 & 0xffff0000u);
    uint32_t l0 = packbf(v.x - fx, v.y - fy);
    uint32_t l1 = packbf(v.z - fz, v.w - fw);
    int chunk = c4f >> 1, within = (c4f & 1) * 8;
    int byte = row * 128 + ((chunk ^ (row & 7)) << 4) + within;
    *(uint2*)(smc + offH + byte) = make_uint2(h0, h1);
    *(uint2*)(smc + offL + byte) = make_uint2(l0, l1);
}
__device__ __forceinline__ void cp16(uint32_t saddr, const void* g) {
    asm volatile("cp.async.cg.shared.global [%0], [%1], 16;" :: "r"(saddr), "l"(g) : "memory");
}
#define CP_COMMIT() asm volatile("cp.async.commit_group;" ::: "memory")
#define CP_WAIT0()  asm volatile("cp.async.wait_group 0;" ::: "memory")

__global__ __launch_bounds__(NT, 1)
void relu_attn_mma5_kernel(const float* __restrict__ Q,
                           const float* __restrict__ K,
                           const float* __restrict__ V,
                           float* __restrict__ ctx,
                           float* __restrict__ attn) {
    extern __shared__ char smc[];
    const uint32_t sb = cvta_smem(smc);

    const int tid  = threadIdx.x;
    const int lane = tid & 31;
    const int w    = tid >> 5;      // 0..15
    const int wq   = w >> 2;        // 0..3: q rows [wq*32, wq*32+32)
    const int wn   = w & 3;         // 0..3: cols [wn*32, wn*32+32) / k-chunk
    const int bh   = blockIdx.y;
    const int q0   = blockIdx.x * BLK;

    const float* Kb = K + (size_t)bh * S_LEN * HDIM;
    const float* Vb = V + (size_t)bh * S_LEN * HDIM;
    float* attng = attn + ((size_t)bh * S_LEN + q0) * S_LEN;
    float* ctxg  = ctx  + ((size_t)bh * S_LEN + q0) * HDIM;

    // ---- stage tile 0 (fp32 cp.async) + split Q ----
    {
        const float4* Kg4 = (const float4*)Kb;
        const float4* Vg4 = (const float4*)Vb;
        #pragma unroll
        for (int it = 0; it < 4; it++) {
            int i = tid + it * NT;
            cp16(sb + STAGE_K + i * 16, Kg4 + i);
            cp16(sb + STAGE_V + i * 16, Vg4 + i);
        }
        CP_COMMIT();
        const float4* Qg4 = (const float4*)(Q + ((size_t)bh * S_LEN + q0) * HDIM);
        #pragma unroll
        for (int it = 0; it < 4; it++) {
            int i = tid + it * NT;
            split_store(smc, OFF_QH, OFF_QL, i >> 4, i & 15, Qg4[i]);
        }
        CP_WAIT0();
    }
    __syncthreads();

    const int aRowL     = lane & 15;
    const int aChunkOff = lane >> 4;
    const int bRowOff   = (lane & 7) + ((lane >> 4) << 3);
    const int bChunkOff = (lane >> 3) & 1;
    const int vRowOff   = (lane & 7) + (((lane >> 3) & 1) << 3);
    const int vChunkOff = lane >> 4;

    float C2[2][8][4];
    #pragma unroll
    for (int g = 0; g < 2; g++)
        #pragma unroll
        for (int t = 0; t < 8; t++)
            #pragma unroll
            for (int k = 0; k < 4; k++) C2[g][t][k] = 0.0f;

    for (int kt = 0; kt < NTILES; kt++) {
        // ---- convert staged fp32 -> bf16 hi/lo tiles ----
        {
            const float4* Ks4 = (const float4*)(smc + STAGE_K);
            const float4* Vs4 = (const float4*)(smc + STAGE_V);
            #pragma unroll
            for (int it = 0; it < 4; it++) {
                int i = tid + it * NT;
                split_store(smc, OFF_KH, OFF_KL, i >> 4, i & 15, Ks4[i]);
            }
            #pragma unroll
            for (int it = 0; it < 4; it++) {
                int i = tid + it * NT;
                split_store(smc, OFF_VH, OFF_VL, i >> 4, i & 15, Vs4[i]);
            }
        }
        __syncthreads();

        // ---- prefetch next tile into staging ----
        if (kt + 1 < NTILES) {
            const float4* Kg4 = (const float4*)(Kb + (size_t)(kt + 1) * BLK * HDIM);
            const float4* Vg4 = (const float4*)(Vb + (size_t)(kt + 1) * BLK * HDIM);
            #pragma unroll
            for (int it = 0; it < 4; it++) {
                int i = tid + it * NT;
                cp16(sb + STAGE_K + i * 16, Kg4 + i);
                cp16(sb + STAGE_V + i * 16, Vg4 + i);
            }
        }
        CP_COMMIT();

        // ---- two 16-col halves: gemm1 half -> epilogue -> gemm2 half ----
        #pragma unroll
        for (int h = 0; h < 2; h++) {
            float C1[2][2][4];
            #pragma unroll
            for (int g = 0; g < 2; g++)
                #pragma unroll
                for (int s = 0; s < 2; s++)
                    #pragma unroll
                    for (int k = 0; k < 4; k++) C1[g][s][k] = 0.0f;

            #pragma unroll
            for (int kc = 0; kc < 4; kc++) {
                uint32_t aH[2][4], aL[2][4];
                #pragma unroll
                for (int g = 0; g < 2; g++) {
                    int arow = wq * 32 + g * 16 + aRowL;
                    int ch = kc * 2 + aChunkOff;
                    uint32_t ad = sb + OFF_QH + arow * 128 + ((ch ^ (arow & 7)) << 4);
                    ldsm4(aH[g], ad);
                    ldsm4(aL[g], ad + 16384);
                }
                int brow = wn * 32 + h * 16 + bRowOff;
                int bch  = kc * 2 + bChunkOff;
                uint32_t bd = sb + OFF_KH + brow * 128 + ((bch ^ (brow & 7)) << 4);
                uint32_t bHf[4], bLf[4];
                ldsm4(bHf, bd);
                ldsm4(bLf, bd + 16384);
                #pragma unroll
                for (int g = 0; g < 2; g++) {
                    mma16816(C1[g][0], aH[g], bHf[0], bHf[1]);
                    mma16816(C1[g][0], aL[g], bHf[0], bHf[1]);
                    mma16816(C1[g][0], aH[g], bLf[0], bLf[1]);
                    mma16816(C1[g][1], aH[g], bHf[2], bHf[3]);
                    mma16816(C1[g][1], aL[g], bHf[2], bHf[3]);
                    mma16816(C1[g][1], aH[g], bLf[2], bLf[3]);
                }
            }

            // epilogue for this 16-col half
            uint32_t ah[2][4], al[2][4];
            #pragma unroll
            for (int g = 0; g < 2; g++) {
                float* ag = attng
                    + (size_t)(wq * 32 + g * 16 + (lane >> 2)) * S_LEN
                    + (size_t)kt * BLK + wn * 32 + h * 16 + (lane & 3) * 2;
                #pragma unroll
                for (int sub = 0; sub < 2; sub++) {
                    float* c = C1[g][sub];
                    float p0 = fmaxf(c[0] * 0.125f, 0.0f);
                    float p1 = fmaxf(c[1] * 0.125f, 0.0f);
                    float p2 = fmaxf(c[2] * 0.125f, 0.0f);
                    float p3 = fmaxf(c[3] * 0.125f, 0.0f);
                    __stcs((float2*)(ag + sub * 8),             make_float2(p0, p1));
                    __stcs((float2*)(ag + sub * 8 + 8 * S_LEN), make_float2(p2, p3));
                    uint32_t h01 = packbf(p0, p1);
                    uint32_t h23 = packbf(p2, p3);
                    float f0 = __uint_as_float(h01 << 16), f1 = __uint_as_float(h01 & 0xffff0000u);
                    float f2 = __uint_as_float(h23 << 16), f3 = __uint_as_float(h23 & 0xffff0000u);
                    ah[g][2 * sub]     = h01;
                    ah[g][2 * sub + 1] = h23;
                    al[g][2 * sub]     = packbf(p0 - f0, p1 - f1);
                    al[g][2 * sub + 1] = packbf(p2 - f2, p3 - f3);
                }
            }

            // gemm2 for this 16-k chunk
            int vrow = wn * 32 + h * 16 + vRowOff;
            #pragma unroll
            for (int ntV = 0; ntV < 4; ntV++) {
                int vch = ntV * 2 + vChunkOff;
                uint32_t vd = sb + OFF_VH + vrow * 128 + ((vch ^ (vrow & 7)) << 4);
                uint32_t bHf[4], bLf[4];
                ldsm4t(bHf, vd);
                ldsm4t(bLf, vd + 16384);
                #pragma unroll
                for (int g = 0; g < 2; g++) {
                    mma16816(C2[g][2 * ntV],     ah[g], bHf[0], bHf[1]);
                    mma16816(C2[g][2 * ntV],     al[g], bHf[0], bHf[1]);
                    mma16816(C2[g][2 * ntV],     ah[g], bLf[0], bLf[1]);
                    mma16816(C2[g][2 * ntV + 1], ah[g], bHf[2], bHf[3]);
                    mma16816(C2[g][2 * ntV + 1], al[g], bHf[2], bHf[3]);
                    mma16816(C2[g][2 * ntV + 1], ah[g], bLf[2], bLf[3]);
                }
            }
        }

        CP_WAIT0();
        __syncthreads();
    }

    // ---- 4-way split-k reduction of C2, then write ctx ----
    float* red = (float*)smc;   // 3 layers of [128][RED_STRIDE] fp32, overlays tiles
    if (wn >= 1) {
        float* layer = red + (size_t)(wn - 1) * RED_LSZ;
        #pragma unroll
        for (int g = 0; g < 2; g++) {
            int r = wq * 32 + g * 16 + (lane >> 2);
            #pragma unroll
            for (int t = 0; t < 8; t++) {
                int col = (t >> 1) * 16 + (t & 1) * 8 + (lane & 3) * 2;
                *(float2*)&layer[(size_t)r * RED_STRIDE + col] =
                    make_float2(C2[g][t][0], C2[g][t][1]);
                *(float2*)&layer[(size_t)(r + 8) * RED_STRIDE + col] =
                    make_float2(C2[g][t][2], C2[g][t][3]);
            }
        }
    }
    __syncthreads();
    if (wn == 0) {
        #pragma unroll
        for (int g = 0; g < 2; g++) {
            int r = wq * 32 + g * 16 + (lane >> 2);
            #pragma unroll
            for (int t = 0; t < 8; t++) {
                int col = (t >> 1) * 16 + (t & 1) * 8 + (lane & 3) * 2;
                float s0 = C2[g][t][0], s1 = C2[g][t][1];
                float s2 = C2[g][t][2], s3 = C2[g][t][3];
                #pragma unroll
                for (int l = 0; l < 3; l++) {
                    float* layer = red + (size_t)l * RED_LSZ;
                    float2 p0 = *(float2*)&layer[(size_t)r * RED_STRIDE + col];
                    float2 p1 = *(float2*)&layer[(size_t)(r + 8) * RED_STRIDE + col];
                    s0 += p0.x; s1 += p0.y; s2 += p1.x; s3 += p1.y;
                }
                *(float2*)&ctxg[(size_t)r * HDIM + col]       = make_float2(s0, s1);
                *(float2*)&ctxg[(size_t)(r + 8) * HDIM + col] = make_float2(s2, s3);
            }
        }
    }
}

extern "C" void kernel_launch(void* const* d_in, const int* in_sizes, int n_in,
                              void* d_out, int out_size) {
    const float* Q = (const float*)d_in[0];
    const float* K = (const float*)d_in[1];
    const float* V = (const float*)d_in[2];
    float* ctx  = (float*)d_out;
    float* attn = (float*)d_out + CTX_ELEMS;

    cudaFuncSetAttribute(relu_attn_mma5_kernel,
                         cudaFuncAttributeMaxDynamicSharedMemorySize, SMEM_BYTES);
    dim3 grid(S_LEN / BLK, NBH);
    relu_attn_mma5_kernel<<<grid, NT, SMEM_BYTES>>>(Q, K, V, ctx, attn);
}

// round 9
// speedup vs baseline: 1.5747x; 1.5747x over previous
#include <cuda_runtime.h>
#include <cstdint>
#include <cstddef>

// B=4,H=16,S=2048,D=64 fp32.  out = [ctx (64*2048*64)] ++ [attn (64*2048*2048)]
// score = QK^T/8 ; attn = relu(score) ; ctx = attn @ V
// bf16x3 emulated-fp32 mma.sync; pre-split K/V scratch; double-buffered cp.async;
// R6 grouped MMA schedule (NOT interleaved).
#define S_LEN 2048
#define HDIM  64
#define BLK   128
#define NT    256
#define NTILES (S_LEN / BLK)
#define NBH   64
#define CTX_ELEMS 8388608LL

#define OFF_QH 0
#define OFF_QL 16384
#define BUF0   32768
#define BUFSTR 65536            // per-tile buffer: KH+0, KL+16K, VH+32K, VL+48K
#define SMEM_BYTES 163840
#define RED_STRIDE 72

// pre-split, pre-swizzled bf16 K/V tiles: [bh][tile][KH|KL|VH|VL each 16KB]
__device__ __align__(16) unsigned char SPLIT_KV[(size_t)NBH * NTILES * 4 * 16384];

__device__ __forceinline__ uint32_t cvta_smem(const void* p) {
    uint32_t a;
    asm("{ .reg .u64 t; cvta.to.shared.u64 t, %1; cvt.u32.u64 %0, t; }" : "=r"(a) : "l"(p));
    return a;
}
__device__ __forceinline__ void ldsm4(uint32_t r[4], uint32_t a) {
    asm volatile("ldmatrix.sync.aligned.m8n8.x4.shared.b16 {%0,%1,%2,%3}, [%4];"
                 : "=r"(r[0]), "=r"(r[1]), "=r"(r[2]), "=r"(r[3]) : "r"(a));
}
__device__ __forceinline__ void ldsm4t(uint32_t r[4], uint32_t a) {
    asm volatile("ldmatrix.sync.aligned.m8n8.x4.trans.shared.b16 {%0,%1,%2,%3}, [%4];"
                 : "=r"(r[0]), "=r"(r[1]), "=r"(r[2]), "=r"(r[3]) : "r"(a));
}
__device__ __forceinline__ void mma16816(float c[4], const uint32_t a[4],
                                         uint32_t b0, uint32_t b1) {
    asm volatile("mma.sync.aligned.m16n8k16.row.col.f32.bf16.bf16.f32 "
                 "{%0,%1,%2,%3}, {%4,%5,%6,%7}, {%8,%9}, {%0,%1,%2,%3};"
                 : "+f"(c[0]), "+f"(c[1]), "+f"(c[2]), "+f"(c[3])
                 : "r"(a[0]), "r"(a[1]), "r"(a[2]), "r"(a[3]), "r"(b0), "r"(b1));
}
__device__ __forceinline__ uint32_t packbf(float lo, float hi) {
    uint32_t d;
    asm("cvt.rn.bf16x2.f32 %0, %1, %2;" : "=r"(d) : "f"(hi), "f"(lo));
    return d;
}
__device__ __forceinline__ void split4(float4 v, uint2& h, uint2& l) {
    uint32_t h0 = packbf(v.x, v.y);
    uint32_t h1 = packbf(v.z, v.w);
    float fx = __uint_as_float(h0 << 16), fy = __uint_as_float(h0 & 0xffff0000u);
    float fz = __uint_as_float(h1 << 16), fw = __uint_as_float(h1 & 0xffff0000u);
    h = make_uint2(h0, h1);
    l = make_uint2(packbf(v.x - fx, v.y - fy), packbf(v.z - fz, v.w - fw));
}
__device__ __forceinline__ int swz_byte(int row, int c4f) {
    int chunk = c4f >> 1, within = (c4f & 1) * 8;
    return row * 128 + ((chunk ^ (row & 7)) << 4) + within;
}
__device__ __forceinline__ void cp16(uint32_t saddr, const void* g) {
    asm volatile("cp.async.cg.shared.global [%0], [%1], 16;" :: "r"(saddr), "l"(g) : "memory");
}
#define CP_COMMIT() asm volatile("cp.async.commit_group;" ::: "memory")
#define CP_WAIT0()  asm volatile("cp.async.wait_group 0;" ::: "memory")

// ============ preprocess: split K/V into swizzled bf16 scratch ============
__global__ __launch_bounds__(NT)
void split_kv_kernel(const float* __restrict__ K, const float* __restrict__ V) {
    const int kt = blockIdx.x, bh = blockIdx.y, tid = threadIdx.x;
    const float4* Kg4 = (const float4*)(K + ((size_t)bh * S_LEN + kt * BLK) * HDIM);
    const float4* Vg4 = (const float4*)(V + ((size_t)bh * S_LEN + kt * BLK) * HDIM);
    unsigned char* out = SPLIT_KV + (size_t)(bh * NTILES + kt) * BUFSTR;
    #pragma unroll
    for (int it = 0; it < 8; it++) {
        int i = tid + it * NT;
        int byte = swz_byte(i >> 4, i & 15);
        uint2 h, l;
        split4(Kg4[i], h, l);
        *(uint2*)(out + byte)         = h;
        *(uint2*)(out + 16384 + byte) = l;
        split4(Vg4[i], h, l);
        *(uint2*)(out + 32768 + byte) = h;
        *(uint2*)(out + 49152 + byte) = l;
    }
}

// ============ main fused kernel ============
__global__ __launch_bounds__(NT, 1)
void relu_attn_mma6_kernel(const float* __restrict__ Q,
                           float* __restrict__ ctx,
                           float* __restrict__ attn) {
    extern __shared__ char smc[];
    const uint32_t sb = cvta_smem(smc);

    const int tid  = threadIdx.x;
    const int lane = tid & 31;
    const int w    = tid >> 5;
    const int wq   = w >> 1;        // 0..3: q rows [wq*32, wq*32+32)
    const int wn   = w & 1;         // 0..1: gemm1 cols [wn*64, wn*64+64)
    const int bh   = blockIdx.y;
    const int q0   = blockIdx.x * BLK;

    const unsigned char* kvb = SPLIT_KV + (size_t)bh * NTILES * BUFSTR;
    float* attng = attn + ((size_t)bh * S_LEN + q0) * S_LEN;
    float* ctxg  = ctx  + ((size_t)bh * S_LEN + q0) * HDIM;

    // ---- stage tile 0 + split Q ----
    {
        #pragma unroll
        for (int it = 0; it < 16; it++) {
            int off = (tid + it * NT) * 16;
            cp16(sb + BUF0 + off, kvb + off);
        }
        CP_COMMIT();
        const float4* Qg4 = (const float4*)(Q + ((size_t)bh * S_LEN + q0) * HDIM);
        #pragma unroll
        for (int it = 0; it < 8; it++) {
            int i = tid + it * NT;
            int byte = swz_byte(i >> 4, i & 15);
            uint2 h, l;
            split4(Qg4[i], h, l);
            *(uint2*)(smc + OFF_QH + byte) = h;
            *(uint2*)(smc + OFF_QL + byte) = l;
        }
        CP_WAIT0();
    }
    __syncthreads();

    const int aRowL     = lane & 15;
    const int aChunkOff = lane >> 4;
    const int bRowOff   = (lane & 7) + ((lane >> 4) << 3);
    const int bChunkOff = (lane >> 3) & 1;
    const int vRowOff   = (lane & 7) + (((lane >> 3) & 1) << 3);
    const int vChunkOff = lane >> 4;

    float C2[2][8][4];
    #pragma unroll
    for (int g = 0; g < 2; g++)
        #pragma unroll
        for (int t = 0; t < 8; t++)
            #pragma unroll
            for (int k = 0; k < 4; k++) C2[g][t][k] = 0.0f;

    for (int kt = 0; kt < NTILES; kt++) {
        const uint32_t cbuf = sb + BUF0 + (uint32_t)(kt & 1) * BUFSTR;

        // prefetch next tile into the other buffer (hidden behind compute)
        if (kt + 1 < NTILES) {
            uint32_t nbuf = sb + BUF0 + (uint32_t)((kt + 1) & 1) * BUFSTR;
            const unsigned char* src = kvb + (size_t)(kt + 1) * BUFSTR;
            #pragma unroll
            for (int it = 0; it < 16; it++) {
                int off = (tid + it * NT) * 16;
                cp16(nbuf + off, src + off);
            }
        }
        CP_COMMIT();

        // ---- gemm1: C1 = Q K^T over warp's 32 rows x 64 cols (R6 order) ----
        float C1[2][8][4];
        #pragma unroll
        for (int g = 0; g < 2; g++)
            #pragma unroll
            for (int t = 0; t < 8; t++)
                #pragma unroll
                for (int k = 0; k < 4; k++) C1[g][t][k] = 0.0f;

        #pragma unroll
        for (int kc = 0; kc < 4; kc++) {
            uint32_t aH[2][4], aL[2][4];
            #pragma unroll
            for (int g = 0; g < 2; g++) {
                int arow = wq * 32 + g * 16 + aRowL;
                int ch = kc * 2 + aChunkOff;
                uint32_t ad = sb + OFF_QH + arow * 128 + ((ch ^ (arow & 7)) << 4);
                ldsm4(aH[g], ad);
                ldsm4(aL[g], ad + 16384);
            }
            #pragma unroll
            for (int nt2 = 0; nt2 < 4; nt2++) {
                int brow = wn * 64 + nt2 * 16 + bRowOff;
                int bch  = kc * 2 + bChunkOff;
                uint32_t bd = cbuf + brow * 128 + ((bch ^ (brow & 7)) << 4);
                uint32_t bHf[4], bLf[4];
                ldsm4(bHf, bd);
                ldsm4(bLf, bd + 16384);
                #pragma unroll
                for (int g = 0; g < 2; g++) {
                    mma16816(C1[g][2 * nt2],     aH[g], bHf[0], bHf[1]);
                    mma16816(C1[g][2 * nt2],     aL[g], bHf[0], bHf[1]);
                    mma16816(C1[g][2 * nt2],     aH[g], bLf[0], bLf[1]);
                    mma16816(C1[g][2 * nt2 + 1], aH[g], bHf[2], bHf[3]);
                    mma16816(C1[g][2 * nt2 + 1], aL[g], bHf[2], bHf[3]);
                    mma16816(C1[g][2 * nt2 + 1], aH[g], bLf[2], bLf[3]);
                }
            }
        }

        // ---- fused epilogue + gemm2, one 16-k-col chunk at a time (R6 order) ----
        const uint32_t vbase = cbuf + 32768;
        #pragma unroll
        for (int nt2 = 0; nt2 < 4; nt2++) {
            uint32_t ah[2][4], al[2][4];
            #pragma unroll
            for (int g = 0; g < 2; g++) {
                float* ag = attng
                    + (size_t)(wq * 32 + g * 16 + (lane >> 2)) * S_LEN
                    + (size_t)kt * BLK + wn * 64 + nt2 * 16 + (lane & 3) * 2;
                #pragma unroll
                for (int sub = 0; sub < 2; sub++) {
                    float* c = C1[g][2 * nt2 + sub];
                    float p0 = fmaxf(c[0] * 0.125f, 0.0f);
                    float p1 = fmaxf(c[1] * 0.125f, 0.0f);
                    float p2 = fmaxf(c[2] * 0.125f, 0.0f);
                    float p3 = fmaxf(c[3] * 0.125f, 0.0f);
                    __stcs((float2*)(ag + sub * 8),             make_float2(p0, p1));
                    __stcs((float2*)(ag + sub * 8 + 8 * S_LEN), make_float2(p2, p3));
                    uint32_t h01 = packbf(p0, p1);
                    uint32_t h23 = packbf(p2, p3);
                    float f0 = __uint_as_float(h01 << 16), f1 = __uint_as_float(h01 & 0xffff0000u);
                    float f2 = __uint_as_float(h23 << 16), f3 = __uint_as_float(h23 & 0xffff0000u);
                    ah[g][2 * sub]     = h01;
                    ah[g][2 * sub + 1] = h23;
                    al[g][2 * sub]     = packbf(p0 - f0, p1 - f1);
                    al[g][2 * sub + 1] = packbf(p2 - f2, p3 - f3);
                }
            }
            int vrow = wn * 64 + nt2 * 16 + vRowOff;
            #pragma unroll
            for (int ntV = 0; ntV < 4; ntV++) {
                int vch = ntV * 2 + vChunkOff;
                uint32_t vd = vbase + vrow * 128 + ((vch ^ (vrow & 7)) << 4);
                uint32_t bHf[4], bLf[4];
                ldsm4t(bHf, vd);
                ldsm4t(bLf, vd + 16384);
                #pragma unroll
                for (int g = 0; g < 2; g++) {
                    mma16816(C2[g][2 * ntV],     ah[g], bHf[0], bHf[1]);
                    mma16816(C2[g][2 * ntV],     al[g], bHf[0], bHf[1]);
                    mma16816(C2[g][2 * ntV],     ah[g], bLf[0], bLf[1]);
                    mma16816(C2[g][2 * ntV + 1], ah[g], bHf[2], bHf[3]);
                    mma16816(C2[g][2 * ntV + 1], al[g], bHf[2], bHf[3]);
                    mma16816(C2[g][2 * ntV + 1], ah[g], bLf[2], bLf[3]);
                }
            }
        }

        CP_WAIT0();
        __syncthreads();
    }

    // ---- split-k reduction of C2 across wn pairs, then write ctx ----
    float* red = (float*)smc;   // overlays tile buffers (done with them)
    if (wn == 1) {
        #pragma unroll
        for (int g = 0; g < 2; g++) {
            int r = wq * 32 + g * 16 + (lane >> 2);
            #pragma unroll
            for (int t = 0; t < 8; t++) {
                int col = (t >> 1) * 16 + (t & 1) * 8 + (lane & 3) * 2;
                *(float2*)&red[(size_t)r * RED_STRIDE + col] =
                    make_float2(C2[g][t][0], C2[g][t][1]);
                *(float2*)&red[(size_t)(r + 8) * RED_STRIDE + col] =
                    make_float2(C2[g][t][2], C2[g][t][3]);
            }
        }
    }
    __syncthreads();
    if (wn == 0) {
        #pragma unroll
        for (int g = 0; g < 2; g++) {
            int r = wq * 32 + g * 16 + (lane >> 2);
            #pragma unroll
            for (int t = 0; t < 8; t++) {
                int col = (t >> 1) * 16 + (t & 1) * 8 + (lane & 3) * 2;
                float2 p0 = *(float2*)&red[(size_t)r * RED_STRIDE + col];
                float2 p1 = *(float2*)&red[(size_t)(r + 8) * RED_STRIDE + col];
                *(float2*)&ctxg[(size_t)r * HDIM + col] =
                    make_float2(C2[g][t][0] + p0.x, C2[g][t][1] + p0.y);
                *(float2*)&ctxg[(size_t)(r + 8) * HDIM + col] =
                    make_float2(C2[g][t][2] + p1.x, C2[g][t][3] + p1.y);
            }
        }
    }
}

extern "C" void kernel_launch(void* const* d_in, const int* in_sizes, int n_in,
                              void* d_out, int out_size) {
    const float* Q = (const float*)d_in[0];
    const float* K = (const float*)d_in[1];
    const float* V = (const float*)d_in[2];
    float* ctx  = (float*)d_out;
    float* attn = (float*)d_out + CTX_ELEMS;

    dim3 pg(NTILES, NBH);
    split_kv_kernel<<<pg, NT>>>(K, V);

    cudaFuncSetAttribute(relu_attn_mma6_kernel,
                         cudaFuncAttributeMaxDynamicSharedMemorySize, SMEM_BYTES);
    dim3 grid(S_LEN / BLK, NBH);
    relu_attn_mma6_kernel<<<grid, NT, SMEM_BYTES>>>(Q, ctx, attn);
}

// round 10
// speedup vs baseline: 2.1058x; 1.3373x over previous
#include <cuda_runtime.h>
#include <cuda_fp16.h>
#include <cstdint>
#include <cstddef>

// B=4,H=16,S=2048,D=64 fp32.  out = [ctx (64*2048*64)] ++ [attn (64*2048*2048)]
// score = QK^T/8 ; attn = relu(score) ; ctx = attn @ V
// fp16 2-pass emulated-fp32 mma.sync (A-side split only): err ~1.5e-4 << 1e-3.
// Pre-converted fp16 K/V scratch; double-buffered cp.async; grouped MMA order.
#define S_LEN 2048
#define HDIM  64
#define BLK   128
#define NT    256
#define NTILES (S_LEN / BLK)
#define NBH   64
#define CTX_ELEMS 8388608LL

#define OFF_QH 0
#define OFF_QL 16384
#define BUF0   32768
#define BUFSTR 32768            // per-tile buffer: KH at +0, VH at +16384
#define SMEM_BYTES 98304
#define RED_STRIDE 72

// pre-converted, pre-swizzled fp16 K/V hi tiles: [bh][tile][KH|VH each 16KB]
__device__ __align__(16) unsigned char SPLIT_KV[(size_t)NBH * NTILES * BUFSTR];

__device__ __forceinline__ uint32_t cvta_smem(const void* p) {
    uint32_t a;
    asm("{ .reg .u64 t; cvta.to.shared.u64 t, %1; cvt.u32.u64 %0, t; }" : "=r"(a) : "l"(p));
    return a;
}
__device__ __forceinline__ void ldsm4(uint32_t r[4], uint32_t a) {
    asm volatile("ldmatrix.sync.aligned.m8n8.x4.shared.b16 {%0,%1,%2,%3}, [%4];"
                 : "=r"(r[0]), "=r"(r[1]), "=r"(r[2]), "=r"(r[3]) : "r"(a));
}
__device__ __forceinline__ void ldsm4t(uint32_t r[4], uint32_t a) {
    asm volatile("ldmatrix.sync.aligned.m8n8.x4.trans.shared.b16 {%0,%1,%2,%3}, [%4];"
                 : "=r"(r[0]), "=r"(r[1]), "=r"(r[2]), "=r"(r[3]) : "r"(a));
}
__device__ __forceinline__ void mmah(float c[4], const uint32_t a[4],
                                     uint32_t b0, uint32_t b1) {
    asm volatile("mma.sync.aligned.m16n8k16.row.col.f32.f16.f16.f32 "
                 "{%0,%1,%2,%3}, {%4,%5,%6,%7}, {%8,%9}, {%0,%1,%2,%3};"
                 : "+f"(c[0]), "+f"(c[1]), "+f"(c[2]), "+f"(c[3])
                 : "r"(a[0]), "r"(a[1]), "r"(a[2]), "r"(a[3]), "r"(b0), "r"(b1));
}
// pack two f32 -> f16x2 (lo arg -> low half, hi arg -> high half)
__device__ __forceinline__ uint32_t packh(float lo, float hi) {
    uint32_t d;
    asm("cvt.rn.f16x2.f32 %0, %1, %2;" : "=r"(d) : "f"(hi), "f"(lo));
    return d;
}
__device__ __forceinline__ int swz_byte(int row, int c4f) {
    int chunk = c4f >> 1, within = (c4f & 1) * 8;
    return row * 128 + ((chunk ^ (row & 7)) << 4) + within;
}
// fp16-convert a float4 (hi only) -> 8 bytes
__device__ __forceinline__ uint2 cvt4h(float4 v) {
    return make_uint2(packh(v.x, v.y), packh(v.z, v.w));
}
// split float4 (scaled) into fp16 hi + fp16 residual lo
__device__ __forceinline__ void split4h(float4 v, float s, uint2& h, uint2& l) {
    v.x *= s; v.y *= s; v.z *= s; v.w *= s;
    uint32_t h0 = packh(v.x, v.y);
    uint32_t h1 = packh(v.z, v.w);
    __half2 hh0 = *(__half2*)&h0, hh1 = *(__half2*)&h1;
    h = make_uint2(h0, h1);
    l = make_uint2(packh(v.x - __low2float(hh0), v.y - __high2float(hh0)),
                   packh(v.z - __low2float(hh1), v.w - __high2float(hh1)));
}
__device__ __forceinline__ void cp16(uint32_t saddr, const void* g) {
    asm volatile("cp.async.cg.shared.global [%0], [%1], 16;" :: "r"(saddr), "l"(g) : "memory");
}
#define CP_COMMIT() asm volatile("cp.async.commit_group;" ::: "memory")
#define CP_WAIT0()  asm volatile("cp.async.wait_group 0;" ::: "memory")

// ============ preprocess: convert K/V hi to swizzled fp16 scratch ============
__global__ __launch_bounds__(NT)
void conv_kv_kernel(const float* __restrict__ K, const float* __restrict__ V) {
    const int kt = blockIdx.x, bh = blockIdx.y, tid = threadIdx.x;
    const float4* Kg4 = (const float4*)(K + ((size_t)bh * S_LEN + kt * BLK) * HDIM);
    const float4* Vg4 = (const float4*)(V + ((size_t)bh * S_LEN + kt * BLK) * HDIM);
    unsigned char* out = SPLIT_KV + (size_t)(bh * NTILES + kt) * BUFSTR;
    #pragma unroll
    for (int it = 0; it < 8; it++) {
        int i = tid + it * NT;
        int byte = swz_byte(i >> 4, i & 15);
        *(uint2*)(out + byte)         = cvt4h(Kg4[i]);
        *(uint2*)(out + 16384 + byte) = cvt4h(Vg4[i]);
    }
}

// ============ main fused kernel ============
__global__ __launch_bounds__(NT, 1)
void relu_attn_mma7_kernel(const float* __restrict__ Q,
                           float* __restrict__ ctx,
                           float* __restrict__ attn) {
    extern __shared__ char smc[];
    const uint32_t sb = cvta_smem(smc);

    const int tid  = threadIdx.x;
    const int lane = tid & 31;
    const int w    = tid >> 5;
    const int wq   = w >> 1;        // 0..3: q rows [wq*32, wq*32+32)
    const int wn   = w & 1;         // 0..1: gemm1 cols [wn*64, wn*64+64)
    const int bh   = blockIdx.y;
    const int q0   = blockIdx.x * BLK;

    const unsigned char* kvb = SPLIT_KV + (size_t)bh * NTILES * BUFSTR;
    float* attng = attn + ((size_t)bh * S_LEN + q0) * S_LEN;
    float* ctxg  = ctx  + ((size_t)bh * S_LEN + q0) * HDIM;

    // ---- stage tile 0 + split Q (scaled by 1/8) ----
    {
        #pragma unroll
        for (int it = 0; it < 8; it++) {
            int off = (tid + it * NT) * 16;
            cp16(sb + BUF0 + off, kvb + off);
        }
        CP_COMMIT();
        const float4* Qg4 = (const float4*)(Q + ((size_t)bh * S_LEN + q0) * HDIM);
        #pragma unroll
        for (int it = 0; it < 8; it++) {
            int i = tid + it * NT;
            int byte = swz_byte(i >> 4, i & 15);
            uint2 h, l;
            split4h(Qg4[i], 0.125f, h, l);
            *(uint2*)(smc + OFF_QH + byte) = h;
            *(uint2*)(smc + OFF_QL + byte) = l;
        }
        CP_WAIT0();
    }
    __syncthreads();

    const int aRowL     = lane & 15;
    const int aChunkOff = lane >> 4;
    const int bRowOff   = (lane & 7) + ((lane >> 4) << 3);
    const int bChunkOff = (lane >> 3) & 1;
    const int vRowOff   = (lane & 7) + (((lane >> 3) & 1) << 3);
    const int vChunkOff = lane >> 4;

    float C2[2][8][4];
    #pragma unroll
    for (int g = 0; g < 2; g++)
        #pragma unroll
        for (int t = 0; t < 8; t++)
            #pragma unroll
            for (int k = 0; k < 4; k++) C2[g][t][k] = 0.0f;

    for (int kt = 0; kt < NTILES; kt++) {
        const uint32_t cbuf = sb + BUF0 + (uint32_t)(kt & 1) * BUFSTR;

        // prefetch next tile into the other buffer (hidden behind compute)
        if (kt + 1 < NTILES) {
            uint32_t nbuf = sb + BUF0 + (uint32_t)((kt + 1) & 1) * BUFSTR;
            const unsigned char* src = kvb + (size_t)(kt + 1) * BUFSTR;
            #pragma unroll
            for (int it = 0; it < 8; it++) {
                int off = (tid + it * NT) * 16;
                cp16(nbuf + off, src + off);
            }
        }
        CP_COMMIT();

        // ---- gemm1: C1 = (Qh+Ql) Kh^T over warp's 32 rows x 64 cols ----
        float C1[2][8][4];
        #pragma unroll
        for (int g = 0; g < 2; g++)
            #pragma unroll
            for (int t = 0; t < 8; t++)
                #pragma unroll
                for (int k = 0; k < 4; k++) C1[g][t][k] = 0.0f;

        #pragma unroll
        for (int kc = 0; kc < 4; kc++) {
            uint32_t aH[2][4], aL[2][4];
            #pragma unroll
            for (int g = 0; g < 2; g++) {
                int arow = wq * 32 + g * 16 + aRowL;
                int ch = kc * 2 + aChunkOff;
                uint32_t ad = sb + OFF_QH + arow * 128 + ((ch ^ (arow & 7)) << 4);
                ldsm4(aH[g], ad);
                ldsm4(aL[g], ad + 16384);
            }
            #pragma unroll
            for (int nt2 = 0; nt2 < 4; nt2++) {
                int brow = wn * 64 + nt2 * 16 + bRowOff;
                int bch  = kc * 2 + bChunkOff;
                uint32_t bd = cbuf + brow * 128 + ((bch ^ (brow & 7)) << 4);
                uint32_t bHf[4];
                ldsm4(bHf, bd);
                #pragma unroll
                for (int g = 0; g < 2; g++) {
                    mmah(C1[g][2 * nt2],     aH[g], bHf[0], bHf[1]);
                    mmah(C1[g][2 * nt2],     aL[g], bHf[0], bHf[1]);
                    mmah(C1[g][2 * nt2 + 1], aH[g], bHf[2], bHf[3]);
                    mmah(C1[g][2 * nt2 + 1], aL[g], bHf[2], bHf[3]);
                }
            }
        }

        // ---- fused epilogue + gemm2, one 16-k-col chunk at a time ----
        const uint32_t vbase = cbuf + 16384;
        #pragma unroll
        for (int nt2 = 0; nt2 < 4; nt2++) {
            uint32_t ah[2][4], al[2][4];
            #pragma unroll
            for (int g = 0; g < 2; g++) {
                float* ag = attng
                    + (size_t)(wq * 32 + g * 16 + (lane >> 2)) * S_LEN
                    + (size_t)kt * BLK + wn * 64 + nt2 * 16 + (lane & 3) * 2;
                #pragma unroll
                for (int sub = 0; sub < 2; sub++) {
                    float* c = C1[g][2 * nt2 + sub];
                    float p0 = fmaxf(c[0], 0.0f);
                    float p1 = fmaxf(c[1], 0.0f);
                    float p2 = fmaxf(c[2], 0.0f);
                    float p3 = fmaxf(c[3], 0.0f);
                    __stcs((float2*)(ag + sub * 8),             make_float2(p0, p1));
                    __stcs((float2*)(ag + sub * 8 + 8 * S_LEN), make_float2(p2, p3));
                    uint32_t h01 = packh(p0, p1);
                    uint32_t h23 = packh(p2, p3);
                    __half2 hh0 = *(__half2*)&h01, hh1 = *(__half2*)&h23;
                    ah[g][2 * sub]     = h01;
                    ah[g][2 * sub + 1] = h23;
                    al[g][2 * sub]     = packh(p0 - __low2float(hh0), p1 - __high2float(hh0));
                    al[g][2 * sub + 1] = packh(p2 - __low2float(hh1), p3 - __high2float(hh1));
                }
            }
            int vrow = wn * 64 + nt2 * 16 + vRowOff;
            #pragma unroll
            for (int ntV = 0; ntV < 4; ntV++) {
                int vch = ntV * 2 + vChunkOff;
                uint32_t vd = vbase + vrow * 128 + ((vch ^ (vrow & 7)) << 4);
                uint32_t bHf[4];
                ldsm4t(bHf, vd);
                #pragma unroll
                for (int g = 0; g < 2; g++) {
                    mmah(C2[g][2 * ntV],     ah[g], bHf[0], bHf[1]);
                    mmah(C2[g][2 * ntV],     al[g], bHf[0], bHf[1]);
                    mmah(C2[g][2 * ntV + 1], ah[g], bHf[2], bHf[3]);
                    mmah(C2[g][2 * ntV + 1], al[g], bHf[2], bHf[3]);
                }
            }
        }

        CP_WAIT0();
        __syncthreads();
    }

    // ---- split-k reduction of C2 across wn pairs, then write ctx ----
    float* red = (float*)smc;   // overlays tile buffers (done with them)
    if (wn == 1) {
        #pragma unroll
        for (int g = 0; g < 2; g++) {
            int r = wq * 32 + g * 16 + (lane >> 2);
            #pragma unroll
            for (int t = 0; t < 8; t++) {
                int col = (t >> 1) * 16 + (t & 1) * 8 + (lane & 3) * 2;
                *(float2*)&red[(size_t)r * RED_STRIDE + col] =
                    make_float2(C2[g][t][0], C2[g][t][1]);
                *(float2*)&red[(size_t)(r + 8) * RED_STRIDE + col] =
                    make_float2(C2[g][t][2], C2[g][t][3]);
            }
        }
    }
    __syncthreads();
    if (wn == 0) {
        #pragma unroll
        for (int g = 0; g < 2; g++) {
            int r = wq * 32 + g * 16 + (lane >> 2);
            #pragma unroll
            for (int t = 0; t < 8; t++) {
                int col = (t >> 1) * 16 + (t & 1) * 8 + (lane & 3) * 2;
                float2 p0 = *(float2*)&red[(size_t)r * RED_STRIDE + col];
                float2 p1 = *(float2*)&red[(size_t)(r + 8) * RED_STRIDE + col];
                *(float2*)&ctxg[(size_t)r * HDIM + col] =
                    make_float2(C2[g][t][0] + p0.x, C2[g][t][1] + p0.y);
                *(float2*)&ctxg[(size_t)(r + 8) * HDIM + col] =
                    make_float2(C2[g][t][2] + p1.x, C2[g][t][3] + p1.y);
            }
        }
    }
}

extern "C" void kernel_launch(void* const* d_in, const int* in_sizes, int n_in,
                              void* d_out, int out_size) {
    const float* Q = (const float*)d_in[0];
    const float* K = (const float*)d_in[1];
    const float* V = (const float*)d_in[2];
    float* ctx  = (float*)d_out;
    float* attn = (float*)d_out + CTX_ELEMS;

    dim3 pg(NTILES, NBH);
    conv_kv_kernel<<<pg, NT>>>(K, V);

    cudaFuncSetAttribute(relu_attn_mma7_kernel,
                         cudaFuncAttributeMaxDynamicSharedMemorySize, SMEM_BYTES);
    dim3 grid(S_LEN / BLK, NBH);
    relu_attn_mma7_kernel<<<grid, NT, SMEM_BYTES>>>(Q, ctx, attn);
}